// round 17
// baseline (speedup 1.0000x reference)
#include <cuda_runtime.h>
#include <cuda_bf16.h>
#include <math_constants.h>

// AttentionMax: correlation[b,s] = <q[b], sub[b,s]>, argmax over s, one-hot out [bz, ns, 1]
// bz=4096, ns=256, d=128, fp32. Memory-bound: 512MB compulsory stream of feat_sub.
//
// R17: R9 record shape (78.6us best / 80.1 mean) with reduce8: one 9-shfl
// reduction per 8 rows instead of two 6-shfl reduce4 chains (12 shfls).
// 25% fewer shuffle issues, single dependent chain per iteration.

#define NS 256
#define D  128

// Streaming load with 256B L2 fetch granularity (evict-first policy).
__device__ __forceinline__ float4 ldcs256(const float4* p)
{
    float4 v;
    asm("ld.global.cs.L2::256B.v4.f32 {%0,%1,%2,%3}, [%4];"
        : "=f"(v.x), "=f"(v.y), "=f"(v.z), "=f"(v.w)
        : "l"(p));
    return v;
}

// Streaming store (evict-first): output is write-once, never re-read.
__device__ __forceinline__ void stcs(float* p, float v)
{
    asm volatile("st.global.cs.f32 [%0], %1;" :: "l"(p), "f"(v) : "memory");
}

__device__ __forceinline__ float dot4(float4 v, float4 q)
{
    float p = v.x * q.x;
    p = fmaf(v.y, q.y, p);
    p = fmaf(v.z, q.z, p);
    p = fmaf(v.w, q.w, p);
    return p;
}

// Fold 8 rows' per-lane partials into full row sums in one pass (9 shfls).
// Result: lane L holds the sum of row base + 4*b16 + 2*b8 + b4 where
// bX = bit X of L; each row's sum is replicated across 4 lanes.
__device__ __forceinline__ float reduce8(const float* p, int lane)
{
    const unsigned FULL = 0xffffffffu;

    // Stage A (xor16): keep rows 0-3 on b16=0 lanes, rows 4-7 on b16=1 lanes.
    bool h16 = (lane & 16) != 0;
    float a[4];
#pragma unroll
    for (int i = 0; i < 4; ++i) {
        float give = h16 ? p[i] : p[i + 4];
        float keep = h16 ? p[i + 4] : p[i];
        a[i] = keep + __shfl_xor_sync(FULL, give, 16);
    }

    // Stage B (xor8): keep {a0,a1} on b8=0 lanes, {a2,a3} on b8=1 lanes.
    bool h8 = (lane & 8) != 0;
    float b[2];
#pragma unroll
    for (int i = 0; i < 2; ++i) {
        float give = h8 ? a[i] : a[i + 2];
        float keep = h8 ? a[i + 2] : a[i];
        b[i] = keep + __shfl_xor_sync(FULL, give, 8);
    }

    // Stage C (xor4): keep b0 on b4=0 lanes, b1 on b4=1 lanes.
    bool h4 = (lane & 4) != 0;
    float give = h4 ? b[0] : b[1];
    float keep = h4 ? b[1] : b[0];
    float acc = keep + __shfl_xor_sync(FULL, give, 4);

    // Remaining lane bits 1,0 hold unreduced chunks: full adds.
    acc += __shfl_xor_sync(FULL, acc, 2);
    acc += __shfl_xor_sync(FULL, acc, 1);
    return acc;
}

__global__ __launch_bounds__(256, 4)
void attention_max_kernel(const float* __restrict__ q,
                          const float* __restrict__ sub,
                          float* __restrict__ out)
{
    const int b    = blockIdx.x;
    const int tid  = threadIdx.x;
    const int warp = tid >> 5;        // 0..7, each warp owns 32 support rows
    const int lane = tid & 31;
    // Row this lane receives from reduce8: 4*b16 + 2*b8 + b4.
    const int myrow = ((lane >> 2) & 1) | ((lane >> 2) & 2) | ((lane >> 2) & 4);
    const unsigned FULL = 0xffffffffu;

    const float4* base = reinterpret_cast<const float4*>(
        sub + ((size_t)b * NS + warp * 32) * D);

    // Deep prologue: 8 row-loads in flight before any dependent work.
    float4 va[4], vb[4];
#pragma unroll
    for (int j = 0; j < 4; ++j)
        va[j] = ldcs256(&base[j * 32 + lane]);
#pragma unroll
    for (int j = 0; j < 4; ++j)
        vb[j] = ldcs256(&base[(4 + j) * 32 + lane]);

    const float4 qc = reinterpret_cast<const float4*>(q + (size_t)b * D)[lane];

    float bestv = -CUDART_INF_F;
    int   besti = 0;

#pragma unroll
    for (int rr = 0; rr < 32; rr += 8) {
        float p[8];

        // Dots for va, then refill va (rows rr+8..rr+11).
#pragma unroll
        for (int j = 0; j < 4; ++j)
            p[j] = dot4(va[j], qc);
        if (rr + 8 < 32) {
#pragma unroll
            for (int j = 0; j < 4; ++j)
                va[j] = ldcs256(&base[(rr + 8 + j) * 32 + lane]);
        }

        // Dots for vb, then refill vb (rows rr+12..rr+15).
#pragma unroll
        for (int j = 0; j < 4; ++j)
            p[4 + j] = dot4(vb[j], qc);
        if (rr + 8 < 32) {
#pragma unroll
            for (int j = 0; j < 4; ++j)
                vb[j] = ldcs256(&base[(rr + 12 + j) * 32 + lane]);
        }

        // Single 9-shfl reduction covering all 8 rows.
        float s = reduce8(p, lane);
        if (s > bestv) { bestv = s; besti = warp * 32 + rr + myrow; }
    }

    // Cross-lane argmax (value max, smaller index wins ties -> first occurrence).
#pragma unroll
    for (int m = 16; m > 0; m >>= 1) {
        float ov = __shfl_xor_sync(FULL, bestv, m);
        int   oi = __shfl_xor_sync(FULL, besti, m);
        if (ov > bestv || (ov == bestv && oi < besti)) { bestv = ov; besti = oi; }
    }

    __shared__ float wval[8];
    __shared__ int   widx[8];

    if (lane == 0) { wval[warp] = bestv; widx[warp] = besti; }
    __syncthreads();

    // Every thread redundantly reduces the 8 warp results (no second barrier).
    float bv = wval[0];
    int   bi = widx[0];
#pragma unroll
    for (int w = 1; w < 8; ++w)
        if (wval[w] > bv) { bv = wval[w]; bi = widx[w]; }

    stcs(out + (size_t)b * NS + tid, (tid == bi) ? 1.0f : 0.0f);
}

extern "C" void kernel_launch(void* const* d_in, const int* in_sizes, int n_in,
                              void* d_out, int out_size)
{
    const float* q   = (const float*)d_in[0];   // [4096, 128]
    const float* sub = (const float*)d_in[1];   // [4096, 256, 128]
    float*       out = (float*)d_out;           // [4096, 256, 1]

    const int bz = in_sizes[0] / D;             // 4096

    attention_max_kernel<<<bz, NS>>>(q, sub, out);
}